// round 15
// baseline (speedup 1.0000x reference)
#include <cuda_runtime.h>

#define ROWS 1024   // B*T
#define IDIM 256
#define HDIM 1024
#define ODIM 256
#define NSPLIT 4

// ---------------- device scratch (no allocations allowed) ----------------
__device__ unsigned g_mk[(ROWS * HDIM) / 32];     // bernoulli mask (verified R6: partitionable, o0^o1)
__device__ float    g_xaug[ROWS * IDIM];
__device__ float    g_h[ROWS * HDIM];
__device__ float    g_part[NSPLIT * ROWS * ODIM]; // split-K partials (4 MB)
__device__ double   g_psum[256];
__device__ int      g_pcnt[256];

// ---------------- threefry2x32, key = (0, 42) ----------------------------
__device__ __forceinline__ unsigned rotl32(unsigned v, int r) {
    return __funnelshift_l(v, v, r);
}

__device__ __forceinline__ void threefry_0_42(unsigned& x0, unsigned& x1) {
    const unsigned k0 = 0u, k1 = 42u;
    const unsigned k2 = k0 ^ k1 ^ 0x1BD11BDAu;
    x0 += k0; x1 += k1;
#define TF_R(r) { x0 += x1; x1 = rotl32(x1, r); x1 ^= x0; }
    TF_R(13) TF_R(15) TF_R(26) TF_R(6)   x0 += k1; x1 += k2 + 1u;
    TF_R(17) TF_R(29) TF_R(16) TF_R(24)  x0 += k2; x1 += k0 + 2u;
    TF_R(13) TF_R(15) TF_R(26) TF_R(6)   x0 += k0; x1 += k1 + 3u;
    TF_R(17) TF_R(29) TF_R(16) TF_R(24)  x0 += k1; x1 += k2 + 4u;
    TF_R(13) TF_R(15) TF_R(26) TF_R(6)   x0 += k2; x1 += k0 + 5u;
#undef TF_R
}

__global__ void mask_kernel(const float* __restrict__ freq) {
    int i = blockIdx.x * blockDim.x + threadIdx.x;   // 0 .. 2^20-1
    float fr = __ldg(&freq[i & 1023]);
    unsigned a0 = 0u, a1 = (unsigned)i;
    threefry_0_42(a0, a1);
    unsigned bits = a0 ^ a1;
    float u = __uint_as_float((bits >> 9) | 0x3f800000u) - 1.0f;
    unsigned b = __ballot_sync(0xffffffffu, u < fr);
    if ((threadIdx.x & 31) == 0) g_mk[i >> 5] = b;
}

// ---------------- argaug v6: v5 arithmetic, LDS.128 x via 4 shifted copies
// xzp4[d][i] = xz[i+d]; lane picks d = xb&3 and loads aligned float4 ->
// identical values in identical FMA order as v5/R7 (bit-exact), fewer instrs.
__global__ void argaug_kernel(const float* __restrict__ x, const float* __restrict__ y) {
    __shared__ float sx[256];
    __shared__ __align__(16) float syz[264];       // syz[4+q] = y[q], zeros outside
    __shared__ __align__(16) float xzp4[4][456];   // shifted copies of padded xz
    __shared__ float rv[8];
    __shared__ int   ri[8];
    __shared__ float red[256];
    __shared__ float s_ny;
    __shared__ float s_bestsim;
    __shared__ int   s_bestK, s_bestS;

    const int row = blockIdx.x;
    const int tid = threadIdx.x;
    const int wid = tid >> 5, lane = tid & 31;

    sx[tid] = x[row * IDIM + tid];
    float yv = y[row * IDIM + tid];
    syz[4 + tid] = yv;
    if (tid < 4) { syz[tid] = 0.0f; syz[260 + tid] = 0.0f; }
    for (int m = tid; m < 456; m += 256) {
        xzp4[0][m] = 0.0f; xzp4[1][m] = 0.0f;
        xzp4[2][m] = 0.0f; xzp4[3][m] = 0.0f;
    }
    red[tid] = yv * yv;
    __syncthreads();
    for (int w = 128; w; w >>= 1) {
        if (tid < w) red[tid] += red[tid + w];
        __syncthreads();
    }
    if (tid == 0) {
        s_ny = sqrtf(red[0]);
        s_bestsim = 0.0f;
        s_bestK = 128; s_bestS = 0;
    }
    __syncthreads();
    const float ny = s_ny;

    const int Ktab[9] = {128, 160, 192, 224, 256, 288, 320, 352, 384};

    for (int it = 0; it < 9; ++it) {
        const int K = Ktab[it];
        const double ratio = 256.0 / (double)K;   // numpy float64 semantics
        for (int j = tid; j < K; j += 256) {
            float v = sx[(int)floor((double)j * ratio)];
            xzp4[0][36 + j] = v;
            xzp4[1][35 + j] = v;
            xzp4[2][34 + j] = v;
            xzp4[3][33 + j] = v;
        }
        __syncthreads();

        float lbest = -3.4e38f;
        int   lidx  = 0x7fffffff;
        const int ns = K + 255;
        for (int s0 = wid * 32; s0 < ns; s0 += 256) {
            const int s = s0 + lane;              // == tid + 256*pass (R7 mapping)
            int qlo = 224 - s0; if (qlo < 0) qlo = 0;
            qlo &= ~3;
            int qhi = K + 254 - s0; if (qhi > 255) qhi = 255;
            const int xb = 36 + s - 255;
            const int d = xb & 3;
            const float4* xv = (const float4*)xzp4[d] + ((xb - d) >> 2);
            float dot = 0.0f, nrm = 0.0f;

#define AA_BLOCK(Q) { \
                float4 xq = xv[(Q) >> 2]; \
                float4 y4 = *(const float4*)&syz[4 + (Q)]; \
                dot = fmaf(xq.x, y4.x, dot); nrm = fmaf(xq.x, xq.x, nrm); \
                dot = fmaf(xq.y, y4.y, dot); nrm = fmaf(xq.y, xq.y, nrm); \
                dot = fmaf(xq.z, y4.z, dot); nrm = fmaf(xq.z, xq.z, nrm); \
                dot = fmaf(xq.w, y4.w, dot); nrm = fmaf(xq.w, xq.w, nrm); }

            int q = qlo;
            for (; q + 4 <= qhi; q += 8) {
                AA_BLOCK(q);
                AA_BLOCK(q + 4);
            }
            if (q <= qhi) AA_BLOCK(q);
#undef AA_BLOCK

            if (s < ns) {
                float sim = dot / (ny * sqrtf(nrm));
                if (sim > lbest) { lbest = sim; lidx = s; }
            }
        }
        // warp-shuffle argmax (R10-12 proven; min-index tiebreak)
#pragma unroll
        for (int o = 16; o; o >>= 1) {
            float ov = __shfl_down_sync(0xffffffffu, lbest, o);
            int   oi = __shfl_down_sync(0xffffffffu, lidx, o);
            if (ov > lbest || (ov == lbest && oi < lidx)) { lbest = ov; lidx = oi; }
        }
        if (lane == 0) { rv[wid] = lbest; ri[wid] = lidx; }
        __syncthreads();
        if (tid == 0) {
            float bb = rv[0]; int bi = ri[0];
#pragma unroll
            for (int w = 1; w < 8; ++w) {
                if (rv[w] > bb || (rv[w] == bb && ri[w] < bi)) { bb = rv[w]; bi = ri[w]; }
            }
            if (it == 0) {
                s_bestK = K; s_bestS = bi;
                if (bb > 0.0f) s_bestsim = bb;
            } else if (s_bestsim < bb) {
                s_bestsim = bb; s_bestK = K; s_bestS = bi;
            }
        }
        __syncthreads();   // also protects xzp4 reuse next iter
    }

    const int K = s_bestK, s = s_bestS;
    const double ratio = 256.0 / (double)K;
    const int k = s + tid - 255;
    float v = 0.0f;
    if (k >= 0 && k < K) v = sx[(int)floor((double)k * ratio)];
    g_xaug[row * IDIM + tid] = v;
}

// ---------------- GEMM1: h = (xaug @ W1 + b1) * mk  (R10, 27us measured) --
__global__ void gemm1_kernel(const float* __restrict__ W1, const float* __restrict__ b1) {
    const int K = IDIM, N = HDIM;
    __shared__ float As[2][16][33];
    __shared__ float Bs[2][32][64];
    const int tid = threadIdx.x;                 // 128
    const int tx = tid & 15, ty = tid >> 4;
    const int rowBase = blockIdx.y * 16, colBase = blockIdx.x * 64;
    const int aRow = tid >> 3, aK4 = tid & 7;
    const int bK = tid >> 4, bC4 = tid & 15;
    const int ty2 = ty * 2;
    const float* A = g_xaug;

    float acc[2][4];
#pragma unroll
    for (int i = 0; i < 2; ++i)
#pragma unroll
        for (int j = 0; j < 4; ++j) acc[i][j] = 0.0f;

    {
        float4 av = *(const float4*)(A + (rowBase + aRow) * K + aK4 * 4);
        As[0][aRow][aK4 * 4 + 0] = av.x;
        As[0][aRow][aK4 * 4 + 1] = av.y;
        As[0][aRow][aK4 * 4 + 2] = av.z;
        As[0][aRow][aK4 * 4 + 3] = av.w;
#pragma unroll
        for (int m = 0; m < 4; ++m) {
            float4 bv = *(const float4*)(W1 + (bK + 8 * m) * N + colBase + bC4 * 4);
            *(float4*)&Bs[0][bK + 8 * m][bC4 * 4] = bv;
        }
    }
    __syncthreads();

    const int NT = K / 32;   // 8
    for (int kt = 0; kt < NT; ++kt) {
        const int cur = kt & 1;
        float4 av, bv0, bv1, bv2, bv3;
        if (kt + 1 < NT) {
            const int k0 = (kt + 1) * 32;
            av  = *(const float4*)(A + (rowBase + aRow) * K + k0 + aK4 * 4);
            bv0 = *(const float4*)(W1 + (k0 + bK +  0) * N + colBase + bC4 * 4);
            bv1 = *(const float4*)(W1 + (k0 + bK +  8) * N + colBase + bC4 * 4);
            bv2 = *(const float4*)(W1 + (k0 + bK + 16) * N + colBase + bC4 * 4);
            bv3 = *(const float4*)(W1 + (k0 + bK + 24) * N + colBase + bC4 * 4);
        }
#pragma unroll
        for (int kk = 0; kk < 32; ++kk) {
            float a0 = As[cur][ty2][kk];
            float a1 = As[cur][ty2 + 1][kk];
            float4 b4 = *(const float4*)&Bs[cur][kk][tx * 4];
            acc[0][0] = fmaf(a0, b4.x, acc[0][0]);
            acc[0][1] = fmaf(a0, b4.y, acc[0][1]);
            acc[0][2] = fmaf(a0, b4.z, acc[0][2]);
            acc[0][3] = fmaf(a0, b4.w, acc[0][3]);
            acc[1][0] = fmaf(a1, b4.x, acc[1][0]);
            acc[1][1] = fmaf(a1, b4.y, acc[1][1]);
            acc[1][2] = fmaf(a1, b4.z, acc[1][2]);
            acc[1][3] = fmaf(a1, b4.w, acc[1][3]);
        }
        if (kt + 1 < NT) {
            const int nxt = cur ^ 1;
            As[nxt][aRow][aK4 * 4 + 0] = av.x;
            As[nxt][aRow][aK4 * 4 + 1] = av.y;
            As[nxt][aRow][aK4 * 4 + 2] = av.z;
            As[nxt][aRow][aK4 * 4 + 3] = av.w;
            *(float4*)&Bs[nxt][bK +  0][bC4 * 4] = bv0;
            *(float4*)&Bs[nxt][bK +  8][bC4 * 4] = bv1;
            *(float4*)&Bs[nxt][bK + 16][bC4 * 4] = bv2;
            *(float4*)&Bs[nxt][bK + 24][bC4 * 4] = bv3;
        }
        __syncthreads();
    }

    float4 b1v = *(const float4*)(b1 + colBase + tx * 4);
#pragma unroll
    for (int i = 0; i < 2; ++i) {
        const int r = rowBase + ty2 + i;
        const int c = colBase + tx * 4;
        const unsigned lin = (unsigned)(r * HDIM + c);
        const unsigned word = g_mk[lin >> 5];
        float4 o;
        o.x = ((word >> ((lin + 0) & 31u)) & 1u) ? (acc[i][0] + b1v.x) : 0.0f;
        o.y = ((word >> ((lin + 1) & 31u)) & 1u) ? (acc[i][1] + b1v.y) : 0.0f;
        o.z = ((word >> ((lin + 2) & 31u)) & 1u) ? (acc[i][2] + b1v.z) : 0.0f;
        o.w = ((word >> ((lin + 3) & 31u)) & 1u) ? (acc[i][3] + b1v.w) : 0.0f;
        *(float4*)(g_h + lin) = o;
    }
}

// ---------------- GEMM2 split-K (R10: 27.5us measured) --------------------
__global__ void gemm2_kernel(const float* __restrict__ W2) {
    const int K = HDIM, N = ODIM;
    __shared__ float As[2][16][33];
    __shared__ float Bs[2][32][64];
    const int tid = threadIdx.x;
    const int tx = tid & 15, ty = tid >> 4;
    const int rowBase = blockIdx.y * 16, colBase = blockIdx.x * 64;
    const int kbase = blockIdx.z * 256;
    const int aRow = tid >> 3, aK4 = tid & 7;
    const int bK = tid >> 4, bC4 = tid & 15;
    const int ty2 = ty * 2;
    const float* A = g_h;

    float acc[2][4];
#pragma unroll
    for (int i = 0; i < 2; ++i)
#pragma unroll
        for (int j = 0; j < 4; ++j) acc[i][j] = 0.0f;

    {
        float4 av = *(const float4*)(A + (rowBase + aRow) * K + kbase + aK4 * 4);
        As[0][aRow][aK4 * 4 + 0] = av.x;
        As[0][aRow][aK4 * 4 + 1] = av.y;
        As[0][aRow][aK4 * 4 + 2] = av.z;
        As[0][aRow][aK4 * 4 + 3] = av.w;
#pragma unroll
        for (int m = 0; m < 4; ++m) {
            float4 bv = *(const float4*)(W2 + (kbase + bK + 8 * m) * N + colBase + bC4 * 4);
            *(float4*)&Bs[0][bK + 8 * m][bC4 * 4] = bv;
        }
    }
    __syncthreads();

    const int NT = 256 / 32;   // 8
    for (int kt = 0; kt < NT; ++kt) {
        const int cur = kt & 1;
        float4 av, bv0, bv1, bv2, bv3;
        if (kt + 1 < NT) {
            const int k0 = kbase + (kt + 1) * 32;
            av  = *(const float4*)(A + (rowBase + aRow) * K + k0 + aK4 * 4);
            bv0 = *(const float4*)(W2 + (k0 + bK +  0) * N + colBase + bC4 * 4);
            bv1 = *(const float4*)(W2 + (k0 + bK +  8) * N + colBase + bC4 * 4);
            bv2 = *(const float4*)(W2 + (k0 + bK + 16) * N + colBase + bC4 * 4);
            bv3 = *(const float4*)(W2 + (k0 + bK + 24) * N + colBase + bC4 * 4);
        }
#pragma unroll
        for (int kk = 0; kk < 32; ++kk) {
            float a0 = As[cur][ty2][kk];
            float a1 = As[cur][ty2 + 1][kk];
            float4 b4 = *(const float4*)&Bs[cur][kk][tx * 4];
            acc[0][0] = fmaf(a0, b4.x, acc[0][0]);
            acc[0][1] = fmaf(a0, b4.y, acc[0][1]);
            acc[0][2] = fmaf(a0, b4.z, acc[0][2]);
            acc[0][3] = fmaf(a0, b4.w, acc[0][3]);
            acc[1][0] = fmaf(a1, b4.x, acc[1][0]);
            acc[1][1] = fmaf(a1, b4.y, acc[1][1]);
            acc[1][2] = fmaf(a1, b4.z, acc[1][2]);
            acc[1][3] = fmaf(a1, b4.w, acc[1][3]);
        }
        if (kt + 1 < NT) {
            const int nxt = cur ^ 1;
            As[nxt][aRow][aK4 * 4 + 0] = av.x;
            As[nxt][aRow][aK4 * 4 + 1] = av.y;
            As[nxt][aRow][aK4 * 4 + 2] = av.z;
            As[nxt][aRow][aK4 * 4 + 3] = av.w;
            *(float4*)&Bs[nxt][bK +  0][bC4 * 4] = bv0;
            *(float4*)&Bs[nxt][bK +  8][bC4 * 4] = bv1;
            *(float4*)&Bs[nxt][bK + 16][bC4 * 4] = bv2;
            *(float4*)&Bs[nxt][bK + 24][bC4 * 4] = bv3;
        }
        __syncthreads();
    }

    float* dst = g_part + (size_t)blockIdx.z * (ROWS * ODIM);
#pragma unroll
    for (int i = 0; i < 2; ++i) {
        const int r = rowBase + ty2 + i;
        const int c = colBase + tx * 4;
        *(float4*)(dst + r * ODIM + c) =
            make_float4(acc[i][0], acc[i][1], acc[i][2], acc[i][3]);
    }
}

// ---------------- epilogue: out = Σ partials + b2 + xaug ; masked MSE ----
__global__ void epilogue_kernel(const float* __restrict__ b2, const float* __restrict__ y,
                                float* __restrict__ outp) {
    __shared__ double sred[256];
    __shared__ int    cred[256];
    const int tid = threadIdx.x;
    const int idx = blockIdx.x * 256 + tid;          // f4 index, 65536 total
    const int c = (idx & 63) * 4;

    const float4* p0 = (const float4*)g_part;
    const float4* p1 = p0 + (ROWS * ODIM / 4);
    const float4* p2 = p1 + (ROWS * ODIM / 4);
    const float4* p3 = p2 + (ROWS * ODIM / 4);

    float4 a = p0[idx], b = p1[idx], cc = p2[idx], d = p3[idx];
    float4 xv = ((const float4*)g_xaug)[idx];
    float4 bv = *(const float4*)(b2 + c);
    float4 yv = ((const float4*)y)[idx];

    float v0 = (a.x + b.x) + (cc.x + d.x) + bv.x + xv.x;
    float v1 = (a.y + b.y) + (cc.y + d.y) + bv.y + xv.y;
    float v2 = (a.z + b.z) + (cc.z + d.z) + bv.z + xv.z;
    float v3 = (a.w + b.w) + (cc.w + d.w) + bv.w + xv.w;

    outp[idx * 4 + 0] = v0;
    outp[idx * 4 + 1] = v1;
    outp[idx * 4 + 2] = v2;
    outp[idx * 4 + 3] = v3;

    double lsum = 0.0; int lcnt = 0;
    if (yv.x != 0.0f) { float e = v0 - yv.x; lsum += (double)e * e; lcnt++; }
    if (yv.y != 0.0f) { float e = v1 - yv.y; lsum += (double)e * e; lcnt++; }
    if (yv.z != 0.0f) { float e = v2 - yv.z; lsum += (double)e * e; lcnt++; }
    if (yv.w != 0.0f) { float e = v3 - yv.w; lsum += (double)e * e; lcnt++; }

    sred[tid] = lsum; cred[tid] = lcnt;
    __syncthreads();
    for (int w = 128; w; w >>= 1) {
        if (tid < w) { sred[tid] += sred[tid + w]; cred[tid] += cred[tid + w]; }
        __syncthreads();
    }
    if (tid == 0) { g_psum[blockIdx.x] = sred[0]; g_pcnt[blockIdx.x] = cred[0]; }
}

__global__ void finalize_kernel(float* __restrict__ loss_out) {
    const int tid = threadIdx.x;   // 256
    __shared__ double ss[256];
    __shared__ int    sc[256];
    ss[tid] = g_psum[tid];
    sc[tid] = g_pcnt[tid];
    __syncthreads();
    for (int w = 128; w; w >>= 1) {
        if (tid < w) { ss[tid] += ss[tid + w]; sc[tid] += sc[tid + w]; }
        __syncthreads();
    }
    if (tid == 0) loss_out[0] = (float)(ss[0] / (double)sc[0]);
}

extern "C" void kernel_launch(void* const* d_in, const int* in_sizes, int n_in,
                              void* d_out, int out_size) {
    const float* x    = (const float*)d_in[0];
    const float* y    = (const float*)d_in[1];
    const float* W1   = (const float*)d_in[2];
    const float* b1   = (const float*)d_in[3];
    const float* W2   = (const float*)d_in[4];
    const float* b2   = (const float*)d_in[5];
    const float* freq = (const float*)d_in[6];

    float* out = (float*)d_out;
    const bool has_loss = (out_size > ROWS * ODIM);
    float* outmat = has_loss ? out + 1 : out;

    mask_kernel<<<4096, 256>>>(freq);
    argaug_kernel<<<1024, 256>>>(x, y);
    gemm1_kernel<<<dim3(HDIM / 64, ROWS / 16), 128>>>(W1, b1);
    gemm2_kernel<<<dim3(ODIM / 64, ROWS / 16, NSPLIT), 128>>>(W2);
    epilogue_kernel<<<256, 256>>>(b2, y, outmat);
    if (has_loss) finalize_kernel<<<1, 256>>>(out);
}

// round 16
// speedup vs baseline: 1.3824x; 1.3824x over previous
#include <cuda_runtime.h>

#define ROWS 1024   // B*T
#define IDIM 256
#define HDIM 1024
#define ODIM 256
#define NSPLIT 4

// ---------------- device scratch (no allocations allowed) ----------------
__device__ unsigned g_mk[(ROWS * HDIM) / 32];     // bernoulli mask (verified R6: partitionable, o0^o1)
__device__ float    g_xaug[ROWS * IDIM];
__device__ float    g_h[ROWS * HDIM];
__device__ float    g_part[NSPLIT * ROWS * ODIM]; // split-K partials (4 MB)
__device__ double   g_psum[256];
__device__ int      g_pcnt[256];

// ---------------- threefry2x32, key = (0, 42) ----------------------------
__device__ __forceinline__ unsigned rotl32(unsigned v, int r) {
    return __funnelshift_l(v, v, r);
}

__device__ __forceinline__ void threefry_0_42(unsigned& x0, unsigned& x1) {
    const unsigned k0 = 0u, k1 = 42u;
    const unsigned k2 = k0 ^ k1 ^ 0x1BD11BDAu;
    x0 += k0; x1 += k1;
#define TF_R(r) { x0 += x1; x1 = rotl32(x1, r); x1 ^= x0; }
    TF_R(13) TF_R(15) TF_R(26) TF_R(6)   x0 += k1; x1 += k2 + 1u;
    TF_R(17) TF_R(29) TF_R(16) TF_R(24)  x0 += k2; x1 += k0 + 2u;
    TF_R(13) TF_R(15) TF_R(26) TF_R(6)   x0 += k0; x1 += k1 + 3u;
    TF_R(17) TF_R(29) TF_R(16) TF_R(24)  x0 += k1; x1 += k2 + 4u;
    TF_R(13) TF_R(15) TF_R(26) TF_R(6)   x0 += k2; x1 += k0 + 5u;
#undef TF_R
}

__global__ void mask_kernel(const float* __restrict__ freq) {
    int i = blockIdx.x * blockDim.x + threadIdx.x;   // 0 .. 2^20-1
    float fr = __ldg(&freq[i & 1023]);
    unsigned a0 = 0u, a1 = (unsigned)i;
    threefry_0_42(a0, a1);
    unsigned bits = a0 ^ a1;
    float u = __uint_as_float((bits >> 9) | 0x3f800000u) - 1.0f;
    unsigned b = __ballot_sync(0xffffffffu, u < fr);
    if ((threadIdx.x & 31) == 0) g_mk[i >> 5] = b;
}

// ---------------- argaug v7: R14/v5 memory layout (proven 206.8us pass),
// + 8-q unroll (same loads/FMA order) + warp-shuffle argmax (R10-12 proven)
__global__ void argaug_kernel(const float* __restrict__ x, const float* __restrict__ y) {
    __shared__ float sx[256];
    __shared__ __align__(16) float syz[264];   // syz[4+q] = y[q], zeros outside
    __shared__ float xzp[456];                 // xzp[36+k] = xs[k], zeros outside
    __shared__ float rv[8];
    __shared__ int   ri[8];
    __shared__ float red[256];
    __shared__ float s_ny;
    __shared__ float s_bestsim;
    __shared__ int   s_bestK, s_bestS;

    const int row = blockIdx.x;
    const int tid = threadIdx.x;
    const int wid = tid >> 5, lane = tid & 31;

    sx[tid] = x[row * IDIM + tid];
    float yv = y[row * IDIM + tid];
    syz[4 + tid] = yv;
    if (tid < 4) { syz[tid] = 0.0f; syz[260 + tid] = 0.0f; }
    // zero xzp fully once; thetas only ever write [36, 36+K) with K ascending
    for (int m = tid; m < 456; m += 256) xzp[m] = 0.0f;
    red[tid] = yv * yv;
    __syncthreads();
    for (int w = 128; w; w >>= 1) {
        if (tid < w) red[tid] += red[tid + w];
        __syncthreads();
    }
    if (tid == 0) {
        s_ny = sqrtf(red[0]);
        s_bestsim = 0.0f;
        s_bestK = 128; s_bestS = 0;
    }
    __syncthreads();
    const float ny = s_ny;

    const int Ktab[9] = {128, 160, 192, 224, 256, 288, 320, 352, 384};

    for (int it = 0; it < 9; ++it) {
        const int K = Ktab[it];
        const double ratio = 256.0 / (double)K;   // numpy float64 semantics
        for (int j = tid; j < K; j += 256)
            xzp[36 + j] = sx[(int)floor((double)j * ratio)];
        __syncthreads();

        float lbest = -3.4e38f;
        int   lidx  = 0x7fffffff;
        const int ns = K + 255;
        for (int s0 = wid * 32; s0 < ns; s0 += 256) {
            const int s = s0 + lane;              // == tid + 256*pass (R7 mapping)
            int qlo = 224 - s0; if (qlo < 0) qlo = 0;
            qlo &= ~3;                            // 4-aligned for LDS.128
            int qhi = K + 254 - s0; if (qhi > 255) qhi = 255;
            const int xb = 36 + s - 255;          // xzp idx of k for q=0
            float dot = 0.0f, nrm = 0.0f;

#define AA_BLOCK(Q) { \
                float4 y4 = *(const float4*)&syz[4 + (Q)]; \
                const float* xp = xzp + xb + (Q); \
                float x0 = xp[0], x1 = xp[1], x2 = xp[2], x3 = xp[3]; \
                dot = fmaf(x0, y4.x, dot); nrm = fmaf(x0, x0, nrm); \
                dot = fmaf(x1, y4.y, dot); nrm = fmaf(x1, x1, nrm); \
                dot = fmaf(x2, y4.z, dot); nrm = fmaf(x2, x2, nrm); \
                dot = fmaf(x3, y4.w, dot); nrm = fmaf(x3, x3, nrm); }

            int q = qlo;
            for (; q + 4 <= qhi; q += 8) {
                AA_BLOCK(q);
                AA_BLOCK(q + 4);
            }
            if (q <= qhi) AA_BLOCK(q);
#undef AA_BLOCK

            if (s < ns) {
                float sim = dot / (ny * sqrtf(nrm));
                if (sim > lbest) { lbest = sim; lidx = s; }
            }
        }
        // warp-shuffle argmax (R10-12 proven; min-index tiebreak)
#pragma unroll
        for (int o = 16; o; o >>= 1) {
            float ov = __shfl_down_sync(0xffffffffu, lbest, o);
            int   oi = __shfl_down_sync(0xffffffffu, lidx, o);
            if (ov > lbest || (ov == lbest && oi < lidx)) { lbest = ov; lidx = oi; }
        }
        if (lane == 0) { rv[wid] = lbest; ri[wid] = lidx; }
        __syncthreads();
        if (tid == 0) {
            float bb = rv[0]; int bi = ri[0];
#pragma unroll
            for (int w = 1; w < 8; ++w) {
                if (rv[w] > bb || (rv[w] == bb && ri[w] < bi)) { bb = rv[w]; bi = ri[w]; }
            }
            if (it == 0) {
                s_bestK = K; s_bestS = bi;
                if (bb > 0.0f) s_bestsim = bb;
            } else if (s_bestsim < bb) {
                s_bestsim = bb; s_bestK = K; s_bestS = bi;
            }
        }
        __syncthreads();   // also protects xzp reuse next iter
    }

    const int K = s_bestK, s = s_bestS;
    const double ratio = 256.0 / (double)K;
    const int k = s + tid - 255;
    float v = 0.0f;
    if (k >= 0 && k < K) v = sx[(int)floor((double)k * ratio)];
    g_xaug[row * IDIM + tid] = v;
}

// ---------------- GEMM1: h = (xaug @ W1 + b1) * mk  (R10, 27us measured) --
__global__ void gemm1_kernel(const float* __restrict__ W1, const float* __restrict__ b1) {
    const int K = IDIM, N = HDIM;
    __shared__ float As[2][16][33];
    __shared__ float Bs[2][32][64];
    const int tid = threadIdx.x;                 // 128
    const int tx = tid & 15, ty = tid >> 4;
    const int rowBase = blockIdx.y * 16, colBase = blockIdx.x * 64;
    const int aRow = tid >> 3, aK4 = tid & 7;
    const int bK = tid >> 4, bC4 = tid & 15;
    const int ty2 = ty * 2;
    const float* A = g_xaug;

    float acc[2][4];
#pragma unroll
    for (int i = 0; i < 2; ++i)
#pragma unroll
        for (int j = 0; j < 4; ++j) acc[i][j] = 0.0f;

    {
        float4 av = *(const float4*)(A + (rowBase + aRow) * K + aK4 * 4);
        As[0][aRow][aK4 * 4 + 0] = av.x;
        As[0][aRow][aK4 * 4 + 1] = av.y;
        As[0][aRow][aK4 * 4 + 2] = av.z;
        As[0][aRow][aK4 * 4 + 3] = av.w;
#pragma unroll
        for (int m = 0; m < 4; ++m) {
            float4 bv = *(const float4*)(W1 + (bK + 8 * m) * N + colBase + bC4 * 4);
            *(float4*)&Bs[0][bK + 8 * m][bC4 * 4] = bv;
        }
    }
    __syncthreads();

    const int NT = K / 32;   // 8
    for (int kt = 0; kt < NT; ++kt) {
        const int cur = kt & 1;
        float4 av, bv0, bv1, bv2, bv3;
        if (kt + 1 < NT) {
            const int k0 = (kt + 1) * 32;
            av  = *(const float4*)(A + (rowBase + aRow) * K + k0 + aK4 * 4);
            bv0 = *(const float4*)(W1 + (k0 + bK +  0) * N + colBase + bC4 * 4);
            bv1 = *(const float4*)(W1 + (k0 + bK +  8) * N + colBase + bC4 * 4);
            bv2 = *(const float4*)(W1 + (k0 + bK + 16) * N + colBase + bC4 * 4);
            bv3 = *(const float4*)(W1 + (k0 + bK + 24) * N + colBase + bC4 * 4);
        }
#pragma unroll
        for (int kk = 0; kk < 32; ++kk) {
            float a0 = As[cur][ty2][kk];
            float a1 = As[cur][ty2 + 1][kk];
            float4 b4 = *(const float4*)&Bs[cur][kk][tx * 4];
            acc[0][0] = fmaf(a0, b4.x, acc[0][0]);
            acc[0][1] = fmaf(a0, b4.y, acc[0][1]);
            acc[0][2] = fmaf(a0, b4.z, acc[0][2]);
            acc[0][3] = fmaf(a0, b4.w, acc[0][3]);
            acc[1][0] = fmaf(a1, b4.x, acc[1][0]);
            acc[1][1] = fmaf(a1, b4.y, acc[1][1]);
            acc[1][2] = fmaf(a1, b4.z, acc[1][2]);
            acc[1][3] = fmaf(a1, b4.w, acc[1][3]);
        }
        if (kt + 1 < NT) {
            const int nxt = cur ^ 1;
            As[nxt][aRow][aK4 * 4 + 0] = av.x;
            As[nxt][aRow][aK4 * 4 + 1] = av.y;
            As[nxt][aRow][aK4 * 4 + 2] = av.z;
            As[nxt][aRow][aK4 * 4 + 3] = av.w;
            *(float4*)&Bs[nxt][bK +  0][bC4 * 4] = bv0;
            *(float4*)&Bs[nxt][bK +  8][bC4 * 4] = bv1;
            *(float4*)&Bs[nxt][bK + 16][bC4 * 4] = bv2;
            *(float4*)&Bs[nxt][bK + 24][bC4 * 4] = bv3;
        }
        __syncthreads();
    }

    float4 b1v = *(const float4*)(b1 + colBase + tx * 4);
#pragma unroll
    for (int i = 0; i < 2; ++i) {
        const int r = rowBase + ty2 + i;
        const int c = colBase + tx * 4;
        const unsigned lin = (unsigned)(r * HDIM + c);
        const unsigned word = g_mk[lin >> 5];
        float4 o;
        o.x = ((word >> ((lin + 0) & 31u)) & 1u) ? (acc[i][0] + b1v.x) : 0.0f;
        o.y = ((word >> ((lin + 1) & 31u)) & 1u) ? (acc[i][1] + b1v.y) : 0.0f;
        o.z = ((word >> ((lin + 2) & 31u)) & 1u) ? (acc[i][2] + b1v.z) : 0.0f;
        o.w = ((word >> ((lin + 3) & 31u)) & 1u) ? (acc[i][3] + b1v.w) : 0.0f;
        *(float4*)(g_h + lin) = o;
    }
}

// ---------------- GEMM2 split-K (R10: 27.5us measured) --------------------
__global__ void gemm2_kernel(const float* __restrict__ W2) {
    const int K = HDIM, N = ODIM;
    __shared__ float As[2][16][33];
    __shared__ float Bs[2][32][64];
    const int tid = threadIdx.x;
    const int tx = tid & 15, ty = tid >> 4;
    const int rowBase = blockIdx.y * 16, colBase = blockIdx.x * 64;
    const int kbase = blockIdx.z * 256;
    const int aRow = tid >> 3, aK4 = tid & 7;
    const int bK = tid >> 4, bC4 = tid & 15;
    const int ty2 = ty * 2;
    const float* A = g_h;

    float acc[2][4];
#pragma unroll
    for (int i = 0; i < 2; ++i)
#pragma unroll
        for (int j = 0; j < 4; ++j) acc[i][j] = 0.0f;

    {
        float4 av = *(const float4*)(A + (rowBase + aRow) * K + kbase + aK4 * 4);
        As[0][aRow][aK4 * 4 + 0] = av.x;
        As[0][aRow][aK4 * 4 + 1] = av.y;
        As[0][aRow][aK4 * 4 + 2] = av.z;
        As[0][aRow][aK4 * 4 + 3] = av.w;
#pragma unroll
        for (int m = 0; m < 4; ++m) {
            float4 bv = *(const float4*)(W2 + (kbase + bK + 8 * m) * N + colBase + bC4 * 4);
            *(float4*)&Bs[0][bK + 8 * m][bC4 * 4] = bv;
        }
    }
    __syncthreads();

    const int NT = 256 / 32;   // 8
    for (int kt = 0; kt < NT; ++kt) {
        const int cur = kt & 1;
        float4 av, bv0, bv1, bv2, bv3;
        if (kt + 1 < NT) {
            const int k0 = kbase + (kt + 1) * 32;
            av  = *(const float4*)(A + (rowBase + aRow) * K + k0 + aK4 * 4);
            bv0 = *(const float4*)(W2 + (k0 + bK +  0) * N + colBase + bC4 * 4);
            bv1 = *(const float4*)(W2 + (k0 + bK +  8) * N + colBase + bC4 * 4);
            bv2 = *(const float4*)(W2 + (k0 + bK + 16) * N + colBase + bC4 * 4);
            bv3 = *(const float4*)(W2 + (k0 + bK + 24) * N + colBase + bC4 * 4);
        }
#pragma unroll
        for (int kk = 0; kk < 32; ++kk) {
            float a0 = As[cur][ty2][kk];
            float a1 = As[cur][ty2 + 1][kk];
            float4 b4 = *(const float4*)&Bs[cur][kk][tx * 4];
            acc[0][0] = fmaf(a0, b4.x, acc[0][0]);
            acc[0][1] = fmaf(a0, b4.y, acc[0][1]);
            acc[0][2] = fmaf(a0, b4.z, acc[0][2]);
            acc[0][3] = fmaf(a0, b4.w, acc[0][3]);
            acc[1][0] = fmaf(a1, b4.x, acc[1][0]);
            acc[1][1] = fmaf(a1, b4.y, acc[1][1]);
            acc[1][2] = fmaf(a1, b4.z, acc[1][2]);
            acc[1][3] = fmaf(a1, b4.w, acc[1][3]);
        }
        if (kt + 1 < NT) {
            const int nxt = cur ^ 1;
            As[nxt][aRow][aK4 * 4 + 0] = av.x;
            As[nxt][aRow][aK4 * 4 + 1] = av.y;
            As[nxt][aRow][aK4 * 4 + 2] = av.z;
            As[nxt][aRow][aK4 * 4 + 3] = av.w;
            *(float4*)&Bs[nxt][bK +  0][bC4 * 4] = bv0;
            *(float4*)&Bs[nxt][bK +  8][bC4 * 4] = bv1;
            *(float4*)&Bs[nxt][bK + 16][bC4 * 4] = bv2;
            *(float4*)&Bs[nxt][bK + 24][bC4 * 4] = bv3;
        }
        __syncthreads();
    }

    float* dst = g_part + (size_t)blockIdx.z * (ROWS * ODIM);
#pragma unroll
    for (int i = 0; i < 2; ++i) {
        const int r = rowBase + ty2 + i;
        const int c = colBase + tx * 4;
        *(float4*)(dst + r * ODIM + c) =
            make_float4(acc[i][0], acc[i][1], acc[i][2], acc[i][3]);
    }
}

// ---------------- epilogue: out = Σ partials + b2 + xaug ; masked MSE ----
__global__ void epilogue_kernel(const float* __restrict__ b2, const float* __restrict__ y,
                                float* __restrict__ outp) {
    __shared__ double sred[256];
    __shared__ int    cred[256];
    const int tid = threadIdx.x;
    const int idx = blockIdx.x * 256 + tid;          // f4 index, 65536 total
    const int c = (idx & 63) * 4;

    const float4* p0 = (const float4*)g_part;
    const float4* p1 = p0 + (ROWS * ODIM / 4);
    const float4* p2 = p1 + (ROWS * ODIM / 4);
    const float4* p3 = p2 + (ROWS * ODIM / 4);

    float4 a = p0[idx], b = p1[idx], cc = p2[idx], d = p3[idx];
    float4 xv = ((const float4*)g_xaug)[idx];
    float4 bv = *(const float4*)(b2 + c);
    float4 yv = ((const float4*)y)[idx];

    float v0 = (a.x + b.x) + (cc.x + d.x) + bv.x + xv.x;
    float v1 = (a.y + b.y) + (cc.y + d.y) + bv.y + xv.y;
    float v2 = (a.z + b.z) + (cc.z + d.z) + bv.z + xv.z;
    float v3 = (a.w + b.w) + (cc.w + d.w) + bv.w + xv.w;

    outp[idx * 4 + 0] = v0;
    outp[idx * 4 + 1] = v1;
    outp[idx * 4 + 2] = v2;
    outp[idx * 4 + 3] = v3;

    double lsum = 0.0; int lcnt = 0;
    if (yv.x != 0.0f) { float e = v0 - yv.x; lsum += (double)e * e; lcnt++; }
    if (yv.y != 0.0f) { float e = v1 - yv.y; lsum += (double)e * e; lcnt++; }
    if (yv.z != 0.0f) { float e = v2 - yv.z; lsum += (double)e * e; lcnt++; }
    if (yv.w != 0.0f) { float e = v3 - yv.w; lsum += (double)e * e; lcnt++; }

    sred[tid] = lsum; cred[tid] = lcnt;
    __syncthreads();
    for (int w = 128; w; w >>= 1) {
        if (tid < w) { sred[tid] += sred[tid + w]; cred[tid] += cred[tid + w]; }
        __syncthreads();
    }
    if (tid == 0) { g_psum[blockIdx.x] = sred[0]; g_pcnt[blockIdx.x] = cred[0]; }
}

__global__ void finalize_kernel(float* __restrict__ loss_out) {
    const int tid = threadIdx.x;   // 256
    __shared__ double ss[256];
    __shared__ int    sc[256];
    ss[tid] = g_psum[tid];
    sc[tid] = g_pcnt[tid];
    __syncthreads();
    for (int w = 128; w; w >>= 1) {
        if (tid < w) { ss[tid] += ss[tid + w]; sc[tid] += sc[tid + w]; }
        __syncthreads();
    }
    if (tid == 0) loss_out[0] = (float)(ss[0] / (double)sc[0]);
}

extern "C" void kernel_launch(void* const* d_in, const int* in_sizes, int n_in,
                              void* d_out, int out_size) {
    const float* x    = (const float*)d_in[0];
    const float* y    = (const float*)d_in[1];
    const float* W1   = (const float*)d_in[2];
    const float* b1   = (const float*)d_in[3];
    const float* W2   = (const float*)d_in[4];
    const float* b2   = (const float*)d_in[5];
    const float* freq = (const float*)d_in[6];

    float* out = (float*)d_out;
    const bool has_loss = (out_size > ROWS * ODIM);
    float* outmat = has_loss ? out + 1 : out;

    mask_kernel<<<4096, 256>>>(freq);
    argaug_kernel<<<1024, 256>>>(x, y);
    gemm1_kernel<<<dim3(HDIM / 64, ROWS / 16), 128>>>(W1, b1);
    gemm2_kernel<<<dim3(ODIM / 64, ROWS / 16, NSPLIT), 128>>>(W2);
    epilogue_kernel<<<256, 256>>>(b2, y, outmat);
    if (has_loss) finalize_kernel<<<1, 256>>>(out);
}